// round 5
// baseline (speedup 1.0000x reference)
#include <cuda_runtime.h>
#include <cuda_bf16.h>
#include <math.h>

// Problem constants
#define BB 256   // batch
#define SS 512   // seq len
#define HH 1024  // hidden
#define EE 256   // input dim
#define CC 128   // num classes

typedef unsigned long long u64;

// ---------------- device scratch (no allocations allowed) ----------------
__device__ float g_Gf[CC * HH];          // emb@Wfx^T + bf
__device__ float g_Gi[CC * HH];          // emb@Wix^T + bi
__device__ float g_Go[CC * HH];          // emb@Wox^T + bo
__device__ float g_Sc[CC * HH];          // sigmoid(emb@Wcx^T + bc)
__device__ u64   g_c2[2][HH * (BB/2)];   // cell state transposed+paired: [buf][n*128 + bpair]
__device__ ulonglong2 g_WD [HH * HH];    // [k][n] = { {wf,wf}, {wi,wi} }  (16MB)
__device__ u64        g_WoD[HH * HH];    // [k][n] = {wo,wo}               (8MB)
__device__ float g_h[BB * HH];           // final hidden [b][h]
__device__ unsigned g_bar[4];            // per-m-group barrier counters

// ---------------- helpers ----------------
__device__ __forceinline__ float sigmoidf_(float x) {
    return 1.0f / (1.0f + __expf(-x));
}
__device__ __forceinline__ u64 pk2(float lo, float hi) {
    u64 r; asm("mov.b64 %0, {%1, %2};" : "=l"(r) : "f"(lo), "f"(hi)); return r;
}
__device__ __forceinline__ u64 pk2b(float v) {
    u64 r; asm("mov.b64 %0, {%1, %1};" : "=l"(r) : "f"(v)); return r;
}
__device__ __forceinline__ void upk2(u64 v, float& lo, float& hi) {
    asm("mov.b64 {%0, %1}, %2;" : "=f"(lo), "=f"(hi) : "l"(v));
}
__device__ __forceinline__ u64 fma2(u64 a, u64 b, u64 c) {
    u64 d; asm("fma.rn.f32x2 %0, %1, %2, %3;" : "=l"(d) : "l"(a), "l"(b), "l"(c)); return d;
}
__device__ __forceinline__ unsigned int smem_u32(const void* p) {
    return (unsigned int)__cvta_generic_to_shared(p);
}
__device__ __forceinline__ void cpa16(void* dst, const void* src) {
    asm volatile("cp.async.cg.shared.global [%0], [%1], 16;\n"
                 :: "r"(smem_u32(dst)), "l"(src));
}
#define CP_COMMIT() asm volatile("cp.async.commit_group;\n" ::: "memory")
#define CP_WAIT0()  asm volatile("cp.async.wait_group 0;\n" ::: "memory")

// per-m-group grid barrier (32 co-resident blocks per group, monotonic counter)
__device__ __forceinline__ void mg_barrier(int mg, unsigned goal) {
    __syncthreads();
    if (threadIdx.x == 0) {
        __threadfence();
        atomicAdd(&g_bar[mg], 1u);
        unsigned v;
        do {
            asm volatile("ld.acquire.gpu.global.u32 %0, [%1];"
                         : "=r"(v) : "l"(g_bar + mg) : "memory");
        } while (v < goal);
    }
    __syncthreads();
}

// ---------------- kernel: zero initial cell state + barrier counters ----------------
__global__ void zero_kernel() {
    int i = blockIdx.x * blockDim.x + threadIdx.x;  // 65536 float4 = 1MB
    reinterpret_cast<float4*>(g_c2[0])[i] = make_float4(0.f, 0.f, 0.f, 0.f);
    if (blockIdx.x == 0 && threadIdx.x < 4) g_bar[threadIdx.x] = 0u;
}

// ---------------- kernel: transpose + duplicate-pack Wfh/Wih ----------------
__global__ __launch_bounds__(256)
void transpose_fi_kernel(const float* __restrict__ Wf, const float* __restrict__ Wi) {
    __shared__ float tf[32][33], ti[32][33];
    const int k0 = blockIdx.x * 32;
    const int n0 = blockIdx.y * 32;
    const int tx = threadIdx.x & 31;
    const int ty = threadIdx.x >> 5;
#pragma unroll
    for (int r = 0; r < 4; r++) {
        const int row = ty + r * 8;
        tf[row][tx] = Wf[(size_t)(n0 + row) * HH + k0 + tx];
        ti[row][tx] = Wi[(size_t)(n0 + row) * HH + k0 + tx];
    }
    __syncthreads();
#pragma unroll
    for (int r = 0; r < 4; r++) {
        const int row = ty + r * 8;   // output k = k0+row, n = n0+tx
        ulonglong2 v;
        v.x = pk2b(tf[tx][row]);
        v.y = pk2b(ti[tx][row]);
        g_WD[(size_t)(k0 + row) * HH + n0 + tx] = v;
    }
}

// ---------------- kernel: transpose + duplicate-pack Woh ----------------
__global__ __launch_bounds__(256)
void transpose_o_kernel(const float* __restrict__ Wo) {
    __shared__ float t[32][33];
    const int k0 = blockIdx.x * 32;
    const int n0 = blockIdx.y * 32;
    const int tx = threadIdx.x & 31;
    const int ty = threadIdx.x >> 5;
#pragma unroll
    for (int r = 0; r < 4; r++) {
        const int row = ty + r * 8;
        t[row][tx] = Wo[(size_t)(n0 + row) * HH + k0 + tx];
    }
    __syncthreads();
#pragma unroll
    for (int r = 0; r < 4; r++) {
        const int row = ty + r * 8;
        g_WoD[(size_t)(k0 + row) * HH + n0 + tx] = pk2b(t[tx][row]);
    }
}

// ---------------- kernel: precompute class->gate tables ----------------
__global__ __launch_bounds__(256)
void tab_kernel(const float* __restrict__ emb,
                const float* __restrict__ Wfx, const float* __restrict__ Wix,
                const float* __restrict__ Wox, const float* __restrict__ Wcx,
                const float* __restrict__ bf,  const float* __restrict__ bi,
                const float* __restrict__ bo,  const float* __restrict__ bc) {
    __shared__ float es[32][33];
    __shared__ float ws[4][32][33];

    const int tid = threadIdx.x;
    const int h0  = blockIdx.x * 32;
    const int c0b = blockIdx.y * 32;
    const int tx  = tid & 31;
    const int ty  = tid >> 5;

    float acc[4][4];
#pragma unroll
    for (int m = 0; m < 4; m++)
#pragma unroll
        for (int q = 0; q < 4; q++) acc[m][q] = 0.f;

    for (int k0 = 0; k0 < EE; k0 += 32) {
        __syncthreads();
        const int ccol  = tid & 31;
        const int rbase = tid >> 5;
#pragma unroll
        for (int rr = 0; rr < 4; rr++) {
            const int r = rbase + rr * 8;
            es[r][ccol]    = emb[(c0b + r) * EE + k0 + ccol];
            ws[0][r][ccol] = Wfx[(h0 + r) * EE + k0 + ccol];
            ws[1][r][ccol] = Wix[(h0 + r) * EE + k0 + ccol];
            ws[2][r][ccol] = Wox[(h0 + r) * EE + k0 + ccol];
            ws[3][r][ccol] = Wcx[(h0 + r) * EE + k0 + ccol];
        }
        __syncthreads();
#pragma unroll
        for (int kk = 0; kk < 32; kk++) {
            const float b0 = ws[0][tx][kk];
            const float b1 = ws[1][tx][kk];
            const float b2 = ws[2][tx][kk];
            const float b3 = ws[3][tx][kk];
#pragma unroll
            for (int q = 0; q < 4; q++) {
                const float a = es[ty + q * 8][kk];
                acc[0][q] = fmaf(a, b0, acc[0][q]);
                acc[1][q] = fmaf(a, b1, acc[1][q]);
                acc[2][q] = fmaf(a, b2, acc[2][q]);
                acc[3][q] = fmaf(a, b3, acc[3][q]);
            }
        }
    }

    const int h = h0 + tx;
    const float vbf = bf[h], vbi = bi[h], vbo = bo[h], vbc = bc[h];
#pragma unroll
    for (int q = 0; q < 4; q++) {
        const int cls = c0b + ty + q * 8;
        g_Gf[cls * HH + h] = acc[0][q] + vbf;
        g_Gi[cls * HH + h] = acc[1][q] + vbi;
        g_Go[cls * HH + h] = acc[2][q] + vbo;
        g_Sc[cls * HH + h] = sigmoidf_(acc[3][q] + vbc);
    }
}

// ---------------- persistent kernel: all 512 steps + final o-gate ----------------
// Tile M=64 (batch), N=32 (hidden). grid (32 n-tiles, 4 m-groups), 256 threads.
// Dynamic smem: a_s u64[2][32][32] (16KB) | w_s ulonglong2[2][32][32] (32KB)
__global__ __launch_bounds__(256, 1)
void persist_kernel(const int* __restrict__ x) {
    extern __shared__ __align__(16) char dynsm[];
    u64        (*a_s)[32][32] = reinterpret_cast<u64(*)[32][32]>(dynsm);
    ulonglong2 (*w_s)[32][32] = reinterpret_cast<ulonglong2(*)[32][32]>(dynsm + 16384);
    u64        (*wo_s)[32][32] = reinterpret_cast<u64(*)[32][32]>(dynsm + 16384);
    __shared__ int cls_s[64];

    const int tid = threadIdx.x;
    const int mg  = blockIdx.y;        // m-group 0..3
    const int M0  = mg * 64;
    const int N0  = blockIdx.x * 32;

    const int tx  = tid & 31;          // n lane
    const int ty  = tid >> 5;          // warp id -> bpair group
    const int mpb = ty * 4;

    const int prow = tid >> 3;         // 0..31 (k row within tile)
    const int pcol = tid & 7;          // 0..7

    const ulonglong2* wSrc = g_WD + (size_t)prow * HH + N0 + pcol * 4;

    // prefetch W tile 0 (constant across steps)
#pragma unroll
    for (int j = 0; j < 4; j++) cpa16(&w_s[0][prow][pcol * 4 + j], wSrc + j);
    CP_COMMIT();

#pragma unroll 1
    for (int t = 0; t < SS; t++) {
        const u64* __restrict__ cin  = g_c2[t & 1];
        u64*       __restrict__ cout = g_c2[(t & 1) ^ 1];
        if (tid < 64) cls_s[tid] = x[(M0 + tid) * SS + t];

        const u64* aSrc = cin + (size_t)prow * (BB/2) + (M0 >> 1) + pcol * 4;
        // prefetch A tile 0
        cpa16(&a_s[0][prow][pcol * 4],     aSrc);
        cpa16(&a_s[0][prow][pcol * 4 + 2], aSrc + 2);
        CP_COMMIT();

        u64 accf[4], acci[4];
#pragma unroll
        for (int p = 0; p < 4; p++) { accf[p] = 0ull; acci[p] = 0ull; }

#pragma unroll 1
        for (int it = 0; it < 32; it++) {
            const int buf = it & 1;
            CP_WAIT0();
            __syncthreads();
            if (it < 31) {
                const size_t aoff = (size_t)(it + 1) * 32 * (BB/2);
                const size_t woff = (size_t)(it + 1) * 32 * HH;
                cpa16(&a_s[buf ^ 1][prow][pcol * 4],     aSrc + aoff);
                cpa16(&a_s[buf ^ 1][prow][pcol * 4 + 2], aSrc + aoff + 2);
#pragma unroll
                for (int j = 0; j < 4; j++)
                    cpa16(&w_s[buf ^ 1][prow][pcol * 4 + j], wSrc + woff + j);
                CP_COMMIT();
            }
#pragma unroll
            for (int kk = 0; kk < 32; kk++) {
                const ulonglong2 w   = w_s[buf][kk][tx];
                const ulonglong2 A01 = *reinterpret_cast<const ulonglong2*>(&a_s[buf][kk][mpb]);
                const ulonglong2 A23 = *reinterpret_cast<const ulonglong2*>(&a_s[buf][kk][mpb + 2]);
                accf[0] = fma2(A01.x, w.x, accf[0]);  acci[0] = fma2(A01.x, w.y, acci[0]);
                accf[1] = fma2(A01.y, w.x, accf[1]);  acci[1] = fma2(A01.y, w.y, acci[1]);
                accf[2] = fma2(A23.x, w.x, accf[2]);  acci[2] = fma2(A23.x, w.y, acci[2]);
                accf[3] = fma2(A23.y, w.x, accf[3]);  acci[3] = fma2(A23.y, w.y, acci[3]);
            }
        }

        // epilogue: gates + cell update
        const int n = N0 + tx;
#pragma unroll
        for (int p = 0; p < 4; p++) {
            const int mp = (M0 >> 1) + mpb + p;
            float flo, fhi, ilo, ihi;
            upk2(accf[p], flo, fhi);
            upk2(acci[p], ilo, ihi);
            float c0o, c1o;
            upk2(cin[(size_t)n * (BB/2) + mp], c0o, c1o);
            const int lm   = 2 * (mpb + p);
            const int cls0 = cls_s[lm];
            const int cls1 = cls_s[lm + 1];
            const float f0 = sigmoidf_(flo + __ldg(&g_Gf[cls0 * HH + n]));
            const float i0 = sigmoidf_(ilo + __ldg(&g_Gi[cls0 * HH + n]));
            const float f1 = sigmoidf_(fhi + __ldg(&g_Gf[cls1 * HH + n]));
            const float i1 = sigmoidf_(ihi + __ldg(&g_Gi[cls1 * HH + n]));
            const float cn0 = __ldg(&g_Sc[cls0 * HH + n]) * i0 + c0o * f0;
            const float cn1 = __ldg(&g_Sc[cls1 * HH + n]) * i1 + c1o * f1;
            cout[(size_t)n * (BB/2) + mp] = pk2(cn0, cn1);
        }

        if (t < SS - 1) {
            // prefetch W tile 0 for next step (constant data, safe pre-barrier)
#pragma unroll
            for (int j = 0; j < 4; j++) cpa16(&w_s[0][prow][pcol * 4 + j], wSrc + j);
            CP_COMMIT();
        }
        mg_barrier(mg, (unsigned)(t + 1) * 32u);
    }

    // ---- final o-gate phase: o from c_prev (g_c2[1]), h = tanh(c_last)*o ----
    {
        const u64* __restrict__ cprev = g_c2[1];
        const u64* __restrict__ clast = g_c2[0];
        const u64* aSrc  = cprev + (size_t)prow * (BB/2) + (M0 >> 1) + pcol * 4;
        const u64* woSrc = g_WoD + (size_t)prow * HH + N0 + pcol * 4;

        // prefetch tile 0 (A + Wo)
        cpa16(&a_s[0][prow][pcol * 4],      aSrc);
        cpa16(&a_s[0][prow][pcol * 4 + 2],  aSrc + 2);
        cpa16(&wo_s[0][prow][pcol * 4],     woSrc);
        cpa16(&wo_s[0][prow][pcol * 4 + 2], woSrc + 2);
        CP_COMMIT();

        u64 acco[4];
#pragma unroll
        for (int p = 0; p < 4; p++) acco[p] = 0ull;

#pragma unroll 1
        for (int it = 0; it < 32; it++) {
            const int buf = it & 1;
            CP_WAIT0();
            __syncthreads();
            if (it < 31) {
                const size_t aoff = (size_t)(it + 1) * 32 * (BB/2);
                const size_t woff = (size_t)(it + 1) * 32 * HH;
                cpa16(&a_s[buf ^ 1][prow][pcol * 4],      aSrc + aoff);
                cpa16(&a_s[buf ^ 1][prow][pcol * 4 + 2],  aSrc + aoff + 2);
                cpa16(&wo_s[buf ^ 1][prow][pcol * 4],     woSrc + woff);
                cpa16(&wo_s[buf ^ 1][prow][pcol * 4 + 2], woSrc + woff + 2);
                CP_COMMIT();
            }
#pragma unroll
            for (int kk = 0; kk < 32; kk++) {
                const u64 wo2 = wo_s[buf][kk][tx];
                const ulonglong2 A01 = *reinterpret_cast<const ulonglong2*>(&a_s[buf][kk][mpb]);
                const ulonglong2 A23 = *reinterpret_cast<const ulonglong2*>(&a_s[buf][kk][mpb + 2]);
                acco[0] = fma2(A01.x, wo2, acco[0]);
                acco[1] = fma2(A01.y, wo2, acco[1]);
                acco[2] = fma2(A23.x, wo2, acco[2]);
                acco[3] = fma2(A23.y, wo2, acco[3]);
            }
        }

        const int n = N0 + tx;
#pragma unroll
        for (int p = 0; p < 4; p++) {
            const int mp = (M0 >> 1) + mpb + p;
            float olo, ohi;
            upk2(acco[p], olo, ohi);
            float cl0, cl1;
            upk2(clast[(size_t)n * (BB/2) + mp], cl0, cl1);
            const int lm   = 2 * (mpb + p);
            const int cls0 = cls_s[lm];   // still holds t=511 classes
            const int cls1 = cls_s[lm + 1];
            const float o0 = sigmoidf_(olo + __ldg(&g_Go[cls0 * HH + n]));
            const float o1 = sigmoidf_(ohi + __ldg(&g_Go[cls1 * HH + n]));
            g_h[(size_t)(2 * mp)     * HH + n] = tanhf(cl0) * o0;
            g_h[(size_t)(2 * mp + 1) * HH + n] = tanhf(cl1) * o1;
        }
    }
}

// ---------------- kernel: logits + log_softmax ----------------
__global__ __launch_bounds__(128)
void logits_kernel(const float* __restrict__ Wph, const float* __restrict__ bp,
                   float* __restrict__ out) {
    const int b = blockIdx.x;
    const int j = threadIdx.x;

    __shared__ __align__(16) float h_s[HH];
    __shared__ float red[128];

    const float4* hv  = reinterpret_cast<const float4*>(&g_h[(size_t)b * HH]);
    float4*       hs4 = reinterpret_cast<float4*>(h_s);
    for (int i = j; i < HH / 4; i += 128) hs4[i] = hv[i];
    __syncthreads();

    float acc = 0.f;
    const float4* w4 = reinterpret_cast<const float4*>(&Wph[(size_t)j * HH]);
#pragma unroll 4
    for (int k = 0; k < HH / 4; k++) {
        const float4 w = w4[k];
        const float4 h = hs4[k];
        acc = fmaf(h.x, w.x, acc);
        acc = fmaf(h.y, w.y, acc);
        acc = fmaf(h.z, w.z, acc);
        acc = fmaf(h.w, w.w, acc);
    }
    const float p = acc + bp[j];

    red[j] = p;
    __syncthreads();
    for (int s2 = 64; s2 > 0; s2 >>= 1) {
        if (j < s2) red[j] = fmaxf(red[j], red[j + s2]);
        __syncthreads();
    }
    const float mx = red[0];
    __syncthreads();
    red[j] = expf(p - mx);
    __syncthreads();
    for (int s2 = 64; s2 > 0; s2 >>= 1) {
        if (j < s2) red[j] += red[j + s2];
        __syncthreads();
    }
    const float lse = logf(red[0]) + mx;
    out[b * CC + j] = p - lse;
}

// ---------------- launcher ----------------
extern "C" void kernel_launch(void* const* d_in, const int* in_sizes, int n_in,
                              void* d_out, int out_size) {
    const int*   x   = (const int*)  d_in[0];
    const float* emb = (const float*)d_in[1];
    const float* Wcx = (const float*)d_in[2];
    const float* bc  = (const float*)d_in[3];
    const float* Wix = (const float*)d_in[4];
    const float* Wih = (const float*)d_in[5];
    const float* bi  = (const float*)d_in[6];
    const float* Wfx = (const float*)d_in[7];
    const float* Wfh = (const float*)d_in[8];
    const float* bf  = (const float*)d_in[9];
    const float* Wox = (const float*)d_in[10];
    const float* Woh = (const float*)d_in[11];
    const float* bo  = (const float*)d_in[12];
    const float* Wph = (const float*)d_in[13];
    const float* bp  = (const float*)d_in[14];
    float* out = (float*)d_out;

    const int dyn_smem = 16384 + 32768;  // A (16KB) + W (32KB)
    cudaFuncSetAttribute(persist_kernel,
                         cudaFuncAttributeMaxDynamicSharedMemorySize, dyn_smem);

    transpose_fi_kernel<<<dim3(32, 32), 256>>>(Wfh, Wih);
    transpose_o_kernel<<<dim3(32, 32), 256>>>(Woh);
    tab_kernel<<<dim3(32, 4), 256>>>(emb, Wfx, Wix, Wox, Wcx, bf, bi, bo, bc);
    zero_kernel<<<256, 256>>>();

    persist_kernel<<<dim3(32, 4), 256, dyn_smem>>>(x);

    logits_kernel<<<BB, 128>>>(Wph, bp, out);
}